// round 5
// baseline (speedup 1.0000x reference)
#include <cuda_runtime.h>
#include <cstdint>

#define T_STEPS 64
#define BATCH   128
#define HID     1024
#define INP     1024
#define KTOT    1025
#define GCOLS   2048
#define SRC_PITCH 1032          // u16 pitch; 1032*2=2064 bytes, 16B aligned
#define ACC_LIM 256.0f

// ---- static device state (no dynamic allocation) ----
__device__ __align__(16) uint16_t g_src[2][GCOLS * SRC_PITCH];
__device__ float    g_C[2][T_STEPS * GCOLS];
__device__ int      g_rngW[256];
__device__ int      g_rngWI[256];
__device__ int      g_rngM[16];
__device__ float    g_hbuf[2][BATCH * HID];
__device__ float    g_acc[6][BATCH * HID];
__device__ uint32_t g_mul[3][BATCH * HID];   // sr(4b) | idx_p<<8 | idx_i<<16

// ---- numpy RandomState(seed).permutation(n), bit-exact ----
__device__ void mt_fill_perm(uint32_t seed, int n, int* out) {
    uint32_t mt[624];
    uint32_t s = seed;
    for (int i = 0; i < 624; i++) { mt[i] = s; s = 1812433253u * (s ^ (s >> 30)) + (uint32_t)i + 1u; }
    int pos = 624;
    int arr[256];
    for (int i = 0; i < n; i++) arr[i] = i;
    for (int i = n - 1; i > 0; i--) {
        uint32_t mask = (uint32_t)i;
        mask |= mask >> 1; mask |= mask >> 2; mask |= mask >> 4; mask |= mask >> 8; mask |= mask >> 16;
        uint32_t j;
        do {
            if (pos >= 624) {
                for (int k = 0; k < 624; k++) {
                    uint32_t y = (mt[k] & 0x80000000u) | (mt[(k + 1) % 624] & 0x7fffffffu);
                    uint32_t v = mt[(k + 397) % 624] ^ (y >> 1);
                    if (y & 1u) v ^= 0x9908b0dfu;
                    mt[k] = v;
                }
                pos = 0;
            }
            uint32_t y = mt[pos++];
            y ^= y >> 11; y ^= (y << 7) & 0x9d2c5680u; y ^= (y << 15) & 0xefc60000u; y ^= y >> 18;
            j = y & mask;
        } while (j > (uint32_t)i);
        int tmp = arr[i]; arr[i] = arr[j]; arr[j] = tmp;
    }
    for (int i = 0; i < n; i++) out[i] = arr[i];
}

__global__ void rng_init_kernel() {
    int t = threadIdx.x;
    if (t == 0) mt_fill_perm(0u, 256, g_rngW);
    else if (t == 1) mt_fill_perm(1u, 256, g_rngWI);
    else if (t == 2) mt_fill_perm(2u, 16, g_rngM);
}

// src = round_half_even((clip(w,-1,1)+1)*0.5*256)
__global__ void quant_kernel(const float* __restrict__ wih, const float* __restrict__ bih,
                             const float* __restrict__ whh, const float* __restrict__ bhh) {
    long long idx = (long long)blockIdx.x * blockDim.x + threadIdx.x;
    const long long total = 2LL * GCOLS * KTOT;
    if (idx >= total) return;
    int m = (int)(idx / (GCOLS * KTOT));
    int r = (int)(idx % (GCOLS * KTOT));
    int j = r / KTOT, k = r % KTOT;
    const float* w = m ? whh : wih;
    const float* b = m ? bhh : bih;
    float v = (k < INP) ? w[(size_t)j * INP + k] : b[j];
    v = fminf(fmaxf(v, -1.0f), 1.0f);
    v = (v + 1.0f) * 0.5f * 256.0f;
    g_src[m][(size_t)j * SRC_PITCH + k] = (uint16_t)__float2int_rn(v);
}

__device__ __forceinline__ int wval(int s, int rp, int ri) {
    return (s > rp) + (s > ri) - 1;
}

// per (m,row): histogram over src values, suffix counts, fold bias-column W'
__global__ void swi_kernel() {
    int m = blockIdx.x >> 11;
    int j = blockIdx.x & 2047;
    __shared__ int hist[257];
    __shared__ int sfx[258];
    for (int i = threadIdx.x; i < 257; i += blockDim.x) hist[i] = 0;
    __syncthreads();
    const uint16_t* row = &g_src[m][(size_t)j * SRC_PITCH];
    for (int k = threadIdx.x; k < KTOT; k += blockDim.x) atomicAdd(&hist[row[k]], 1);
    __syncthreads();
    if (threadIdx.x == 0) {
        int s = 0; sfx[257] = 0;
        for (int v = 256; v >= 0; v--) { s += hist[v]; sfx[v] = s; }
    }
    __syncthreads();
    int sb = (int)row[INP];
    for (int t = threadIdx.x; t < T_STEPS; t += blockDim.x) {
        int ri = g_rngWI[t], rp = g_rngW[t];
        g_C[m][t * GCOLS + j] = (float)(1025 - sfx[ri + 1] + wval(sb, rp, ri));
    }
}

__global__ void state_init_kernel(const float* __restrict__ hx0) {
    int e = blockIdx.x * blockDim.x + threadIdx.x;
    if (e >= BATCH * HID) return;
    g_hbuf[0][e] = hx0[e];
#pragma unroll
    for (int i = 0; i < 6; i++) g_acc[i][e] = 0.0f;
#pragma unroll
    for (int i = 0; i < 3; i++) g_mul[i][e] = 10u;   // sr=[0,1,0,1] -> 0b1010
}

__device__ __forceinline__ float clampA(float v) { return fminf(fmaxf(v, -ACC_LIM), ACC_LIM); }

__device__ __forceinline__ uint32_t pack01(float4 v) {
    return (uint32_t)v.x | ((uint32_t)v.y << 8) | ((uint32_t)v.z << 16) | ((uint32_t)v.w << 24);
}

__device__ __forceinline__ uint32_t packw_pair(uint32_t two_u16, int rp, int ri) {
    int s0 = (int)(two_u16 & 0xFFFFu);
    int s1 = (int)(two_u16 >> 16);
    return ((uint32_t)wval(s0, rp, ri) & 0xFFu) | (((uint32_t)wval(s1, rp, ri) & 0xFFu) << 8);
}

__device__ __forceinline__ float fsu_mul_upd(uint32_t& m, float in0, float in1) {
    uint32_t sr = m & 0xFu;
    sr = (sr >> 1) | (((uint32_t)in1) << 3);
    int cnt = __popc(sr) * 4;
    uint32_t ip = (m >> 8) & 0xFFu;
    uint32_t ii = (m >> 16) & 0xFFu;
    float bp = (cnt > g_rngM[ip & 15u]) ? 1.0f : 0.0f;
    float bi = (cnt > g_rngM[ii & 15u]) ? 1.0f : 0.0f;
    float outv = in0 * bp + (1.0f - in0) * (1.0f - bi);
    uint32_t i0 = (uint32_t)in0;
    ip += i0; ii += 1u - i0;
    m = sr | ((ip & 0xFFu) << 8) | ((ii & 0xFFu) << 16);
    return outv;
}

// fused: both dp4a GEMMs (ih+hh, f+n halves) for a 32x32 (b,j) tile + FSU update
__global__ __launch_bounds__(256) void step_kernel(int t, const float* __restrict__ x_bits,
                                                   float* __restrict__ out) {
    __shared__ uint32_t sAx[32][33];
    __shared__ uint32_t sAh[32][33];
    __shared__ __align__(16) uint32_t sW[2][32][64];
    __shared__ float gsm[2][2][32][32];   // [ih/hh][f/n][b][j]

    const int tid = threadIdx.x;
    const int j0 = blockIdx.x * 32;
    const int b0 = blockIdx.y * 32;
    const int rp = g_rngW[t];
    const int ri = g_rngWI[t];

    const float* hin  = g_hbuf[t & 1];
    float*       hout = g_hbuf[(t + 1) & 1];

    const int r0 = (tid / 16) * 2;
    const int c0 = (tid % 16) * 4;

    const int arow = tid >> 3;
    const int akf  = tid & 7;
    const int wcol = tid & 63;
    const int wgrp = tid >> 6;
    const int jj   = (wcol < 32) ? (j0 + wcol) : (HID + j0 + wcol - 32);
    const uint16_t* srcih = &g_src[0][(size_t)jj * SRC_PITCH];
    const uint16_t* srchh = &g_src[1][(size_t)jj * SRC_PITCH];
    const float* xrow = x_bits + ((size_t)t * BATCH + (b0 + arow)) * INP;
    const float* hrow = hin + (size_t)(b0 + arow) * HID;

    int acc[2][2][4];
#pragma unroll
    for (int g = 0; g < 2; g++)
#pragma unroll
        for (int r = 0; r < 2; r++)
#pragma unroll
            for (int c = 0; c < 4; c++) acc[g][r][c] = 0;

    for (int kt = 0; kt < 8; kt++) {
        const int k0 = kt * 128;
#pragma unroll
        for (int i = 0; i < 4; i++) {
            int kk = k0 + i * 32 + akf * 4;
            float4 xv = *(const float4*)(xrow + kk);
            float4 hv = *(const float4*)(hrow + kk);
            int kg = i * 8 + akf;
            sAx[kg][arow] = pack01(xv);
            sAh[kg][arow] = pack01(hv);
        }
#pragma unroll
        for (int l = 0; l < 4; l++) {
            int kk = k0 + wgrp * 32 + l * 8;
            uint4 qih = *(const uint4*)(srcih + kk);
            uint4 qhh = *(const uint4*)(srchh + kk);
            int kg = wgrp * 8 + l * 2;
            sW[0][kg][wcol]     = packw_pair(qih.x, rp, ri) | (packw_pair(qih.y, rp, ri) << 16);
            sW[0][kg + 1][wcol] = packw_pair(qih.z, rp, ri) | (packw_pair(qih.w, rp, ri) << 16);
            sW[1][kg][wcol]     = packw_pair(qhh.x, rp, ri) | (packw_pair(qhh.y, rp, ri) << 16);
            sW[1][kg + 1][wcol] = packw_pair(qhh.z, rp, ri) | (packw_pair(qhh.w, rp, ri) << 16);
        }
        __syncthreads();
#pragma unroll 8
        for (int kg = 0; kg < 32; kg++) {
            int ax0 = (int)sAx[kg][r0];
            int ax1 = (int)sAx[kg][r0 + 1];
            int ah0 = (int)sAh[kg][r0];
            int ah1 = (int)sAh[kg][r0 + 1];
            uint4 wih = *(const uint4*)&sW[0][kg][c0];
            uint4 whh = *(const uint4*)&sW[1][kg][c0];
            int wi_[4] = {(int)wih.x, (int)wih.y, (int)wih.z, (int)wih.w};
            int wh_[4] = {(int)whh.x, (int)whh.y, (int)whh.z, (int)whh.w};
#pragma unroll
            for (int c = 0; c < 4; c++) {
                acc[0][0][c] = __dp4a(ax0, wi_[c], acc[0][0][c]);
                acc[0][1][c] = __dp4a(ax1, wi_[c], acc[0][1][c]);
                acc[1][0][c] = __dp4a(ah0, wh_[c], acc[1][0][c]);
                acc[1][1][c] = __dp4a(ah1, wh_[c], acc[1][1][c]);
            }
        }
        __syncthreads();
    }

#pragma unroll
    for (int g = 0; g < 2; g++)
#pragma unroll
        for (int r = 0; r < 2; r++)
#pragma unroll
            for (int c = 0; c < 4; c++) {
                int col = c0 + c;
                gsm[g][col >> 5][r0 + r][col & 31] = (float)acc[g][r][c];
            }
    __syncthreads();

#pragma unroll
    for (int i = 0; i < 4; i++) {
        int idx = tid + 256 * i;
        int bb = idx >> 5;
        int jl = idx & 31;
        int b = b0 + bb;
        int j = j0 + jl;
        int e = b * HID + j;

        float gi_f = gsm[0][0][bb][jl] + g_C[0][t * GCOLS + j];
        float gi_n = gsm[0][1][bb][jl] + g_C[0][t * GCOLS + HID + j];
        float gh_f = gsm[1][0][bb][jl] + g_C[1][t * GCOLS + j];
        float gh_n = gsm[1][1][bb][jl] + g_C[1][t * GCOLS + HID + j];

        float h  = hin[e];
        float a1 = g_acc[0][e], a2 = g_acc[1][e], a3 = g_acc[2][e];
        float a4 = g_acc[3][e], a5 = g_acc[4][e], a6 = g_acc[5][e];
        uint32_t m1 = g_mul[0][e], m2 = g_mul[1][e], m3 = g_mul[2][e];

        a1 = clampA(a1 + (gi_f + gh_f) - 1024.5f);
        float fg_in = (a1 >= 1.0f) ? 1.0f : 0.0f;  a1 -= fg_in;

        a2 = clampA(a2 + fg_in + 1.0f);
        float fg = (a2 >= 2.0f) ? 1.0f : 0.0f;     a2 -= 2.0f * fg;

        a3 = clampA(a3 + gh_n - 512.0f);
        float hnb = (a3 >= 1.0f) ? 1.0f : 0.0f;    a3 -= hnb;

        float ng_prod = fsu_mul_upd(m1, fg, hnb);

        a4 = clampA(a4 + gi_n - 512.0f);
        float inb = (a4 >= 1.0f) ? 1.0f : 0.0f;    a4 -= inb;

        a5 = clampA(a5 + (inb + ng_prod) - 0.5f);
        float ng = (a5 >= 1.0f) ? 1.0f : 0.0f;     a5 -= ng;

        float fgi_prod = fsu_mul_upd(m2, 1.0f - fg, ng);
        float fg_prod  = fsu_mul_upd(m3, fg, h);

        a6 = clampA(a6 + (ng + fgi_prod + fg_prod) - 1.0f);
        float hy = (a6 >= 1.0f) ? 1.0f : 0.0f;     a6 -= hy;

        g_acc[0][e] = a1; g_acc[1][e] = a2; g_acc[2][e] = a3;
        g_acc[3][e] = a4; g_acc[4][e] = a5; g_acc[5][e] = a6;
        g_mul[0][e] = m1; g_mul[1][e] = m2; g_mul[2][e] = m3;

        hout[e] = hy;
        out[((size_t)t * BATCH + b) * HID + j] = hy;
    }
}

extern "C" void kernel_launch(void* const* d_in, const int* in_sizes, int n_in,
                              void* d_out, int out_size) {
    const float* x_bits = (const float*)d_in[0];
    const float* hx0    = (const float*)d_in[1];
    const float* wih    = (const float*)d_in[2];
    const float* bih    = (const float*)d_in[3];
    const float* whh    = (const float*)d_in[4];
    const float* bhh    = (const float*)d_in[5];
    float* out = (float*)d_out;

    rng_init_kernel<<<1, 32>>>();

    const long long qtotal = 2LL * GCOLS * KTOT;
    quant_kernel<<<(int)((qtotal + 255) / 256), 256>>>(wih, bih, whh, bhh);

    swi_kernel<<<2 * GCOLS, 128>>>();

    state_init_kernel<<<(BATCH * HID + 255) / 256, 256>>>(hx0);

    dim3 grid(HID / 32, BATCH / 32);
    for (int t = 0; t < T_STEPS; t++) {
        step_kernel<<<grid, 256>>>(t, x_bits, out);
    }
}

// round 6
// speedup vs baseline: 2.0918x; 2.0918x over previous
#include <cuda_runtime.h>
#include <cstdint>

#define T_STEPS 64
#define BATCH   128
#define HID     1024
#define INP     1024
#define KTOT    1025
#define GCOLS   2048
#define SRC_PITCH 1032          // u16 pitch
#define ACC_LIM 256.0f
#define WPITCH  144             // smem row pitch (bytes) for s8 tiles, conflict-free

// ---- static device state (no dynamic allocation) ----
__device__ __align__(16) uint16_t g_src[2][GCOLS * SRC_PITCH];   // quantized weights (u16)
__device__ float    g_C[2][T_STEPS * GCOLS];                     // per-(t,col) gate constant
__device__ int      g_rngW[256];
__device__ int      g_rngWI[256];
__device__ int      g_rngM[16];
__device__ __align__(16) uint2    g_wpi[T_STEPS][2][GCOLS][32];  // bitplanes (wp,wi) per 32-k word
__device__ __align__(16) uint8_t  g_x8[T_STEPS][BATCH][INP];     // x as s8 {0,1}
__device__ __align__(16) uint8_t  g_h8[2][BATCH][HID];           // h double buffer, s8 {0,1}
__device__ float    g_acc[6][BATCH * HID];
__device__ uint32_t g_mul[3][BATCH * HID];   // sr(4b) | idx_p<<8 | idx_i<<16

// ---- numpy RandomState(seed).permutation(n), bit-exact ----
__device__ void mt_fill_perm(uint32_t seed, int n, int* out) {
    uint32_t mt[624];
    uint32_t s = seed;
    for (int i = 0; i < 624; i++) { mt[i] = s; s = 1812433253u * (s ^ (s >> 30)) + (uint32_t)i + 1u; }
    int pos = 624;
    int arr[256];
    for (int i = 0; i < n; i++) arr[i] = i;
    for (int i = n - 1; i > 0; i--) {
        uint32_t mask = (uint32_t)i;
        mask |= mask >> 1; mask |= mask >> 2; mask |= mask >> 4; mask |= mask >> 8; mask |= mask >> 16;
        uint32_t j;
        do {
            if (pos >= 624) {
                for (int k = 0; k < 624; k++) {
                    uint32_t y = (mt[k] & 0x80000000u) | (mt[(k + 1) % 624] & 0x7fffffffu);
                    uint32_t v = mt[(k + 397) % 624] ^ (y >> 1);
                    if (y & 1u) v ^= 0x9908b0dfu;
                    mt[k] = v;
                }
                pos = 0;
            }
            uint32_t y = mt[pos++];
            y ^= y >> 11; y ^= (y << 7) & 0x9d2c5680u; y ^= (y << 15) & 0xefc60000u; y ^= y >> 18;
            j = y & mask;
        } while (j > (uint32_t)i);
        int tmp = arr[i]; arr[i] = arr[j]; arr[j] = tmp;
    }
    for (int i = 0; i < n; i++) out[i] = arr[i];
}

__global__ void rng_init_kernel() {
    int t = threadIdx.x;
    if (t == 0) mt_fill_perm(0u, 256, g_rngW);
    else if (t == 1) mt_fill_perm(1u, 256, g_rngWI);
    else if (t == 2) mt_fill_perm(2u, 16, g_rngM);
}

// src = round_half_even((clip(w,-1,1)+1)*0.5*256)
__global__ void quant_kernel(const float* __restrict__ wih, const float* __restrict__ bih,
                             const float* __restrict__ whh, const float* __restrict__ bhh) {
    long long idx = (long long)blockIdx.x * blockDim.x + threadIdx.x;
    const long long total = 2LL * GCOLS * KTOT;
    if (idx >= total) return;
    int m = (int)(idx / (GCOLS * KTOT));
    int r = (int)(idx % (GCOLS * KTOT));
    int j = r / KTOT, k = r % KTOT;
    const float* w = m ? whh : wih;
    const float* b = m ? bhh : bih;
    float v = (k < INP) ? w[(size_t)j * INP + k] : b[j];
    v = fminf(fmaxf(v, -1.0f), 1.0f);
    v = (v + 1.0f) * 0.5f * 256.0f;
    g_src[m][(size_t)j * SRC_PITCH + k] = (uint16_t)__float2int_rn(v);
}

__device__ __forceinline__ int wval(int s, int rp, int ri) {
    return (s > rp) + (s > ri) - 1;
}

// per (m,row): histogram over src values, suffix counts, fold bias-column W'
__global__ void swi_kernel() {
    int m = blockIdx.x >> 11;
    int j = blockIdx.x & 2047;
    __shared__ int hist[257];
    __shared__ int sfx[258];
    for (int i = threadIdx.x; i < 257; i += blockDim.x) hist[i] = 0;
    __syncthreads();
    const uint16_t* row = &g_src[m][(size_t)j * SRC_PITCH];
    for (int k = threadIdx.x; k < KTOT; k += blockDim.x) atomicAdd(&hist[row[k]], 1);
    __syncthreads();
    if (threadIdx.x == 0) {
        int s = 0; sfx[257] = 0;
        for (int v = 256; v >= 0; v--) { s += hist[v]; sfx[v] = s; }
    }
    __syncthreads();
    int sb = (int)row[INP];
    for (int t = threadIdx.x; t < T_STEPS; t += blockDim.x) {
        int ri = g_rngWI[t], rp = g_rngW[t];
        g_C[m][t * GCOLS + j] = (float)(1025 - sfx[ri + 1] + wval(sb, rp, ri));
    }
}

// bitplanes: wp bit k = (src > rngW[t]), wi bit k = (src > rngWI[t]); one warp per (m,gcol)
__global__ __launch_bounds__(256) void plane_pack_kernel() {
    __shared__ int rw[64], ri2[64];
    int tid = threadIdx.x;
    if (tid < 64) rw[tid] = g_rngW[tid];
    else if (tid < 128) ri2[tid - 64] = g_rngWI[tid - 64];
    __syncthreads();
    int wg = blockIdx.x * 8 + (tid >> 5);
    int m = wg >> 11;
    int gcol = wg & 2047;
    int lane = tid & 31;
    const uint16_t* row = &g_src[m][(size_t)gcol * SRC_PITCH];
    for (int gw = 0; gw < 32; gw++) {
        int s = (int)row[gw * 32 + lane];
        uint32_t myp[2], myi[2];
#pragma unroll
        for (int t = 0; t < 64; t++) {
            uint32_t bp = __ballot_sync(0xFFFFFFFFu, s > rw[t]);
            uint32_t bi = __ballot_sync(0xFFFFFFFFu, s > ri2[t]);
            if ((t & 31) == lane) { myp[t >> 5] = bp; myi[t >> 5] = bi; }
        }
#pragma unroll
        for (int h = 0; h < 2; h++) {
            int tt = h * 32 + lane;
            g_wpi[tt][m][gcol][gw] = make_uint2(myp[h], myi[h]);
        }
    }
}

// x float {0,1} -> s8 bytes, 4 per thread
__global__ void xpack_kernel(const float* __restrict__ x) {
    long long i = (long long)blockIdx.x * blockDim.x + threadIdx.x;
    long long base = i * 4;
    const long long total = (long long)T_STEPS * BATCH * INP;
    if (base >= total) return;
    float4 v = *(const float4*)(x + base);
    uchar4 o;
    o.x = (uint8_t)(int)v.x; o.y = (uint8_t)(int)v.y;
    o.z = (uint8_t)(int)v.z; o.w = (uint8_t)(int)v.w;
    *(uchar4*)(&g_x8[0][0][0] + base) = o;
}

__global__ void state_init_kernel(const float* __restrict__ hx0) {
    int e = blockIdx.x * blockDim.x + threadIdx.x;
    if (e >= BATCH * HID) return;
    (&g_h8[0][0][0])[e] = (uint8_t)(int)hx0[e];
#pragma unroll
    for (int i = 0; i < 6; i++) g_acc[i][e] = 0.0f;
#pragma unroll
    for (int i = 0; i < 3; i++) g_mul[i][e] = 10u;   // sr=[0,1,0,1]
}

__device__ __forceinline__ float clampA(float v) { return fminf(fmaxf(v, -ACC_LIM), ACC_LIM); }

__device__ __forceinline__ float fsu_mul_upd(uint32_t& m, float in0, float in1) {
    uint32_t sr = m & 0xFu;
    sr = (sr >> 1) | (((uint32_t)in1) << 3);
    int cnt = __popc(sr) * 4;
    uint32_t ip = (m >> 8) & 0xFFu;
    uint32_t ii = (m >> 16) & 0xFFu;
    float bp = (cnt > g_rngM[ip & 15u]) ? 1.0f : 0.0f;
    float bi = (cnt > g_rngM[ii & 15u]) ? 1.0f : 0.0f;
    float outv = in0 * bp + (1.0f - in0) * (1.0f - bi);
    uint32_t i0 = (uint32_t)in0;
    ip += i0; ii += 1u - i0;
    m = sr | ((ip & 0xFFu) << 8) | ((ii & 0xFFu) << 16);
    return outv;
}

__device__ __forceinline__ void mma_s8(int* d, const uint32_t* a, const uint32_t* b) {
    asm volatile(
        "mma.sync.aligned.m16n8k32.row.col.s32.s8.s8.s32 "
        "{%0,%1,%2,%3}, {%4,%5,%6,%7}, {%8,%9}, {%0,%1,%2,%3};"
        : "+r"(d[0]), "+r"(d[1]), "+r"(d[2]), "+r"(d[3])
        : "r"(a[0]), "r"(a[1]), "r"(a[2]), "r"(a[3]), "r"(b[0]), "r"(b[1]));
}

// fused step: bitplane->s8 expansion + IMMA GEMMs (ih & hh) + FSU elementwise
// grid (32 j-blocks, 4 b-blocks), 512 threads
__global__ __launch_bounds__(512) void step_kernel(int t, float* __restrict__ out) {
    __shared__ __align__(16) uint8_t sX[32 * WPITCH];
    __shared__ __align__(16) uint8_t sH[32 * WPITCH];
    __shared__ __align__(16) uint8_t sW[128 * WPITCH];
    __shared__ float gsm[2][2][32][32];   // [ih/hh][f/n][b][j]

    const int tid = threadIdx.x;
    const int j0 = blockIdx.x * 32;
    const int b0 = blockIdx.y * 32;
    const int lane = tid & 31;
    const int warp = tid >> 5;
    const int mat = warp >> 3;            // 0: ih (x), 1: hh (h)
    const int mtile = (warp >> 2) & 1;    // 16-row half of the 32-row b tile
    const int npair = warp & 3;           // 16 gate-cols

    // --- weight expansion mapping: thread -> (col-row ec in [0,128), word ew in [0,4)) ---
    const int ec = tid >> 2;
    const int ew = tid & 3;
    const int em = ec >> 6;
    const int egcol = ((ec >> 5) & 1) * HID + j0 + (ec & 31);
    const uint2* wrow = g_wpi[t][em][egcol];
    uint8_t* wdst = &sW[ec * WPITCH + ew * 32];

    // --- A copy mapping ---
    const int cr = (tid & 255) >> 3;
    const int cs = tid & 7;
    const uint8_t* asrc = (tid < 256) ? &g_x8[t][b0 + cr][0] : &g_h8[t & 1][b0 + cr][0];
    uint8_t* adst = ((tid < 256) ? &sX[0] : &sH[0]) + cr * WPITCH + cs * 16;

    // --- mma fragment addresses ---
    const uint8_t* sA = mat ? sH : sX;
    const int abase = (mtile * 16 + (lane >> 2)) * WPITCH + (lane & 3) * 4;
    const int bbase0 = (mat * 64 + (2 * npair) * 8 + (lane >> 2)) * WPITCH + (lane & 3) * 4;
    const int bbase1 = bbase0 + 8 * WPITCH;

    int d[2][4] = {{0, 0, 0, 0}, {0, 0, 0, 0}};

    for (int kt = 0; kt < 8; kt++) {
        // expand 32 weights (one plane word pair) into s8 bytes {-1,0,1}
        uint2 pw = wrow[kt * 4 + ew];
#pragma unroll
        for (int nib = 0; nib < 8; nib++) {
            uint32_t p4 = (pw.x >> (nib * 4)) & 0xFu;
            uint32_t i4 = (pw.y >> (nib * 4)) & 0xFu;
            uint32_t s = ((p4 * 0x00204081u) & 0x01010101u) + ((i4 * 0x00204081u) & 0x01010101u);
            *(uint32_t*)(wdst + nib * 4) = (s + 0x7F7F7F7Fu) ^ 0x80808080u;  // per-byte -1
        }
        // copy A tile chunk (128 K bytes per row)
        *(uint4*)adst = *(const uint4*)(asrc + kt * 128 + cs * 16);
        __syncthreads();

#pragma unroll
        for (int ks = 0; ks < 4; ks++) {
            const int kb = ks * 32;
            uint32_t a[4];
            a[0] = *(const uint32_t*)(sA + abase + kb);
            a[1] = *(const uint32_t*)(sA + abase + 8 * WPITCH + kb);
            a[2] = *(const uint32_t*)(sA + abase + kb + 16);
            a[3] = *(const uint32_t*)(sA + abase + 8 * WPITCH + kb + 16);
            uint32_t br0[2], br1[2];
            br0[0] = *(const uint32_t*)(sW + bbase0 + kb);
            br0[1] = *(const uint32_t*)(sW + bbase0 + kb + 16);
            br1[0] = *(const uint32_t*)(sW + bbase1 + kb);
            br1[1] = *(const uint32_t*)(sW + bbase1 + kb + 16);
            mma_s8(d[0], a, br0);
            mma_s8(d[1], a, br1);
        }
        __syncthreads();
    }

    // --- epilogue: d fragments -> gsm ---
#pragma unroll
    for (int tt = 0; tt < 2; tt++) {
        int ntile = 2 * npair + tt;
        int half = ntile >> 2;
        int cb = (ntile * 8 + (lane & 3) * 2) & 31;
        int rb = mtile * 16 + (lane >> 2);
        gsm[mat][half][rb][cb]         = (float)d[tt][0];
        gsm[mat][half][rb][cb + 1]     = (float)d[tt][1];
        gsm[mat][half][rb + 8][cb]     = (float)d[tt][2];
        gsm[mat][half][rb + 8][cb + 1] = (float)d[tt][3];
    }
    __syncthreads();

    // --- fused FSU elementwise (2 elements / thread) ---
#pragma unroll
    for (int i = 0; i < 2; i++) {
        int idx = tid + 512 * i;
        int bb = idx >> 5;
        int jl = idx & 31;
        int b = b0 + bb;
        int j = j0 + jl;
        int e = b * HID + j;

        float gi_f = gsm[0][0][bb][jl] + g_C[0][t * GCOLS + j];
        float gi_n = gsm[0][1][bb][jl] + g_C[0][t * GCOLS + HID + j];
        float gh_f = gsm[1][0][bb][jl] + g_C[1][t * GCOLS + j];
        float gh_n = gsm[1][1][bb][jl] + g_C[1][t * GCOLS + HID + j];

        float h  = (float)g_h8[t & 1][b][j];
        float a1 = g_acc[0][e], a2 = g_acc[1][e], a3 = g_acc[2][e];
        float a4 = g_acc[3][e], a5 = g_acc[4][e], a6 = g_acc[5][e];
        uint32_t m1 = g_mul[0][e], m2 = g_mul[1][e], m3 = g_mul[2][e];

        a1 = clampA(a1 + (gi_f + gh_f) - 1024.5f);
        float fg_in = (a1 >= 1.0f) ? 1.0f : 0.0f;  a1 -= fg_in;

        a2 = clampA(a2 + fg_in + 1.0f);
        float fg = (a2 >= 2.0f) ? 1.0f : 0.0f;     a2 -= 2.0f * fg;

        a3 = clampA(a3 + gh_n - 512.0f);
        float hnb = (a3 >= 1.0f) ? 1.0f : 0.0f;    a3 -= hnb;

        float ng_prod = fsu_mul_upd(m1, fg, hnb);

        a4 = clampA(a4 + gi_n - 512.0f);
        float inb = (a4 >= 1.0f) ? 1.0f : 0.0f;    a4 -= inb;

        a5 = clampA(a5 + (inb + ng_prod) - 0.5f);
        float ng = (a5 >= 1.0f) ? 1.0f : 0.0f;     a5 -= ng;

        float fgi_prod = fsu_mul_upd(m2, 1.0f - fg, ng);
        float fg_prod  = fsu_mul_upd(m3, fg, h);

        a6 = clampA(a6 + (ng + fgi_prod + fg_prod) - 1.0f);
        float hy = (a6 >= 1.0f) ? 1.0f : 0.0f;     a6 -= hy;

        g_acc[0][e] = a1; g_acc[1][e] = a2; g_acc[2][e] = a3;
        g_acc[3][e] = a4; g_acc[4][e] = a5; g_acc[5][e] = a6;
        g_mul[0][e] = m1; g_mul[1][e] = m2; g_mul[2][e] = m3;

        g_h8[(t + 1) & 1][b][j] = (uint8_t)(int)hy;
        out[((size_t)t * BATCH + b) * HID + j] = hy;
    }
}

extern "C" void kernel_launch(void* const* d_in, const int* in_sizes, int n_in,
                              void* d_out, int out_size) {
    const float* x_bits = (const float*)d_in[0];
    const float* hx0    = (const float*)d_in[1];
    const float* wih    = (const float*)d_in[2];
    const float* bih    = (const float*)d_in[3];
    const float* whh    = (const float*)d_in[4];
    const float* bhh    = (const float*)d_in[5];
    float* out = (float*)d_out;

    rng_init_kernel<<<1, 32>>>();

    const long long qtotal = 2LL * GCOLS * KTOT;
    quant_kernel<<<(int)((qtotal + 255) / 256), 256>>>(wih, bih, whh, bhh);

    swi_kernel<<<2 * GCOLS, 128>>>();

    plane_pack_kernel<<<512, 256>>>();

    const long long xtotal = (long long)T_STEPS * BATCH * INP;
    xpack_kernel<<<(int)((xtotal / 4 + 255) / 256), 256>>>(x_bits);

    state_init_kernel<<<(BATCH * HID + 255) / 256, 256>>>(hx0);

    dim3 grid(HID / 32, BATCH / 32);
    for (int t = 0; t < T_STEPS; t++) {
        step_kernel<<<grid, 512>>>(t, out);
    }
}

// round 7
// speedup vs baseline: 2.7249x; 1.3026x over previous
#include <cuda_runtime.h>
#include <cstdint>

#define T_STEPS 64
#define BATCH   128
#define HID     1024
#define INP     1024
#define KTOT    1025
#define GCOLS   2048
#define SRC_PITCH 1032          // u16 pitch
#define ACC_LIM 256.0f

// smem stage layout (XOR-swizzled 128B rows):
//   sX: 32*128 = 4096,  sH: 4096 (at +4096),  sW: 128*128 = 16384 (at +8192)
//   stage stride 24576, two stages = 49152 bytes total
#define STAGE_STRIDE 24576
#define SX_OFF 0
#define SH_OFF 4096
#define SW_OFF 8192

// ---- static device state (no dynamic allocation) ----
__device__ __align__(16) uint16_t g_src[2][GCOLS * SRC_PITCH];   // quantized weights (u16)
__device__ float    g_C[2][T_STEPS * GCOLS];                     // per-(t,col) gate constant
__device__ int      g_rngW[256];
__device__ int      g_rngWI[256];
__device__ int      g_rngM[16];
__device__ __align__(16) int8_t   g_w8[(size_t)T_STEPS * 2 * GCOLS * 1024]; // expanded W' in {-1,0,1}
__device__ __align__(16) uint8_t  g_x8[T_STEPS][BATCH][INP];     // x as s8 {0,1}
__device__ __align__(16) uint8_t  g_h8[2][BATCH][HID];           // h double buffer, s8 {0,1}
__device__ float    g_acc[6][BATCH * HID];
__device__ uint32_t g_mul[3][BATCH * HID];   // sr(4b) | idx_p<<8 | idx_i<<16

// ---- numpy RandomState(seed).permutation(n), bit-exact ----
__device__ void mt_fill_perm(uint32_t seed, int n, int* out) {
    uint32_t mt[624];
    uint32_t s = seed;
    for (int i = 0; i < 624; i++) { mt[i] = s; s = 1812433253u * (s ^ (s >> 30)) + (uint32_t)i + 1u; }
    int pos = 624;
    int arr[256];
    for (int i = 0; i < n; i++) arr[i] = i;
    for (int i = n - 1; i > 0; i--) {
        uint32_t mask = (uint32_t)i;
        mask |= mask >> 1; mask |= mask >> 2; mask |= mask >> 4; mask |= mask >> 8; mask |= mask >> 16;
        uint32_t j;
        do {
            if (pos >= 624) {
                for (int k = 0; k < 624; k++) {
                    uint32_t y = (mt[k] & 0x80000000u) | (mt[(k + 1) % 624] & 0x7fffffffu);
                    uint32_t v = mt[(k + 397) % 624] ^ (y >> 1);
                    if (y & 1u) v ^= 0x9908b0dfu;
                    mt[k] = v;
                }
                pos = 0;
            }
            uint32_t y = mt[pos++];
            y ^= y >> 11; y ^= (y << 7) & 0x9d2c5680u; y ^= (y << 15) & 0xefc60000u; y ^= y >> 18;
            j = y & mask;
        } while (j > (uint32_t)i);
        int tmp = arr[i]; arr[i] = arr[j]; arr[j] = tmp;
    }
    for (int i = 0; i < n; i++) out[i] = arr[i];
}

__global__ void rng_init_kernel() {
    int t = threadIdx.x;
    if (t == 0) mt_fill_perm(0u, 256, g_rngW);
    else if (t == 1) mt_fill_perm(1u, 256, g_rngWI);
    else if (t == 2) mt_fill_perm(2u, 16, g_rngM);
}

// src = round_half_even((clip(w,-1,1)+1)*0.5*256)
__global__ void quant_kernel(const float* __restrict__ wih, const float* __restrict__ bih,
                             const float* __restrict__ whh, const float* __restrict__ bhh) {
    long long idx = (long long)blockIdx.x * blockDim.x + threadIdx.x;
    const long long total = 2LL * GCOLS * KTOT;
    if (idx >= total) return;
    int m = (int)(idx / (GCOLS * KTOT));
    int r = (int)(idx % (GCOLS * KTOT));
    int j = r / KTOT, k = r % KTOT;
    const float* w = m ? whh : wih;
    const float* b = m ? bhh : bih;
    float v = (k < INP) ? w[(size_t)j * INP + k] : b[j];
    v = fminf(fmaxf(v, -1.0f), 1.0f);
    v = (v + 1.0f) * 0.5f * 256.0f;
    g_src[m][(size_t)j * SRC_PITCH + k] = (uint16_t)__float2int_rn(v);
}

__device__ __forceinline__ int wval(int s, int rp, int ri) {
    return (s > rp) + (s > ri) - 1;
}

// per (m,row): histogram over src values, suffix counts, fold bias-column W'
__global__ void swi_kernel() {
    int m = blockIdx.x >> 11;
    int j = blockIdx.x & 2047;
    __shared__ int hist[257];
    __shared__ int sfx[258];
    for (int i = threadIdx.x; i < 257; i += blockDim.x) hist[i] = 0;
    __syncthreads();
    const uint16_t* row = &g_src[m][(size_t)j * SRC_PITCH];
    for (int k = threadIdx.x; k < KTOT; k += blockDim.x) atomicAdd(&hist[row[k]], 1);
    __syncthreads();
    if (threadIdx.x == 0) {
        int s = 0; sfx[257] = 0;
        for (int v = 256; v >= 0; v--) { s += hist[v]; sfx[v] = s; }
    }
    __syncthreads();
    int sb = (int)row[INP];
    for (int t = threadIdx.x; t < T_STEPS; t += blockDim.x) {
        int ri = g_rngWI[t], rp = g_rngW[t];
        g_C[m][t * GCOLS + j] = (float)(1025 - sfx[ri + 1] + wval(sb, rp, ri));
    }
}

// expand W' for all 64 t: one thread per 16 output bytes
__device__ __forceinline__ uint32_t exp4(uint32_t lo, uint32_t hi, int rp, int ri) {
    int s0 = (int)(lo & 0xFFFFu), s1 = (int)(lo >> 16);
    int s2 = (int)(hi & 0xFFFFu), s3 = (int)(hi >> 16);
    uint32_t b0 = (uint32_t)wval(s0, rp, ri) & 0xFFu;
    uint32_t b1 = (uint32_t)wval(s1, rp, ri) & 0xFFu;
    uint32_t b2 = (uint32_t)wval(s2, rp, ri) & 0xFFu;
    uint32_t b3 = (uint32_t)wval(s3, rp, ri) & 0xFFu;
    return b0 | (b1 << 8) | (b2 << 16) | (b3 << 24);
}

__global__ __launch_bounds__(256) void expand_kernel() {
    int idx = blockIdx.x * 256 + threadIdx.x;   // 16,777,216 threads
    int k16  = idx & 63;
    int gcol = (idx >> 6) & 2047;
    int m    = (idx >> 17) & 1;
    int t    = idx >> 18;
    int rp = g_rngW[t], ri = g_rngWI[t];
    const uint16_t* src = &g_src[m][(size_t)gcol * SRC_PITCH + k16 * 16];
    uint4 q0 = *(const uint4*)src;
    uint4 q1 = *(const uint4*)(src + 8);
    uint4 o;
    o.x = exp4(q0.x, q0.y, rp, ri);
    o.y = exp4(q0.z, q0.w, rp, ri);
    o.z = exp4(q1.x, q1.y, rp, ri);
    o.w = exp4(q1.z, q1.w, rp, ri);
    *(uint4*)(g_w8 + (size_t)idx * 16) = o;
}

// x float {0,1} -> s8 bytes, 4 per thread
__global__ void xpack_kernel(const float* __restrict__ x) {
    long long i = (long long)blockIdx.x * blockDim.x + threadIdx.x;
    long long base = i * 4;
    const long long total = (long long)T_STEPS * BATCH * INP;
    if (base >= total) return;
    float4 v = *(const float4*)(x + base);
    uchar4 o;
    o.x = (uint8_t)(int)v.x; o.y = (uint8_t)(int)v.y;
    o.z = (uint8_t)(int)v.z; o.w = (uint8_t)(int)v.w;
    *(uchar4*)(&g_x8[0][0][0] + base) = o;
}

__global__ void state_init_kernel(const float* __restrict__ hx0) {
    int e = blockIdx.x * blockDim.x + threadIdx.x;
    if (e >= BATCH * HID) return;
    (&g_h8[0][0][0])[e] = (uint8_t)(int)hx0[e];
#pragma unroll
    for (int i = 0; i < 6; i++) g_acc[i][e] = 0.0f;
#pragma unroll
    for (int i = 0; i < 3; i++) g_mul[i][e] = 10u;   // sr=[0,1,0,1]
}

__device__ __forceinline__ float clampA(float v) { return fminf(fmaxf(v, -ACC_LIM), ACC_LIM); }

__device__ __forceinline__ float fsu_mul_upd(uint32_t& m, float in0, float in1) {
    uint32_t sr = m & 0xFu;
    sr = (sr >> 1) | (((uint32_t)in1) << 3);
    int cnt = __popc(sr) * 4;
    uint32_t ip = (m >> 8) & 0xFFu;
    uint32_t ii = (m >> 16) & 0xFFu;
    float bp = (cnt > g_rngM[ip & 15u]) ? 1.0f : 0.0f;
    float bi = (cnt > g_rngM[ii & 15u]) ? 1.0f : 0.0f;
    float outv = in0 * bp + (1.0f - in0) * (1.0f - bi);
    uint32_t i0 = (uint32_t)in0;
    ip += i0; ii += 1u - i0;
    m = sr | ((ip & 0xFFu) << 8) | ((ii & 0xFFu) << 16);
    return outv;
}

__device__ __forceinline__ void mma_s8(int* d, const uint32_t* a, const uint32_t* b) {
    asm volatile(
        "mma.sync.aligned.m16n8k32.row.col.s32.s8.s8.s32 "
        "{%0,%1,%2,%3}, {%4,%5,%6,%7}, {%8,%9}, {%0,%1,%2,%3};"
        : "+r"(d[0]), "+r"(d[1]), "+r"(d[2]), "+r"(d[3])
        : "r"(a[0]), "r"(a[1]), "r"(a[2]), "r"(a[3]), "r"(b[0]), "r"(b[1]));
}

#define CP_ASYNC16(dst_u32, src_ptr) \
    asm volatile("cp.async.cg.shared.global [%0], [%1], 16;" :: "r"(dst_u32), "l"(src_ptr))
#define CP_COMMIT() asm volatile("cp.async.commit_group;" ::)
#define CP_WAIT1()  asm volatile("cp.async.wait_group 1;" ::)
#define CP_WAIT0()  asm volatile("cp.async.wait_group 0;" ::)

// swizzle: within a 128B row, 16B chunk index ^= (row & 7)
__device__ __forceinline__ uint32_t swz(int row, int colbyte) {
    return (uint32_t)(row * 128 + (colbyte ^ ((row & 7) << 4)));
}

// fused step: cp.async double-buffered loads + IMMA GEMMs (ih & hh) + FSU elementwise
// grid (32 j-blocks, 4 b-blocks), 512 threads
__global__ __launch_bounds__(512) void step_kernel(int t, float* __restrict__ out) {
    __shared__ __align__(16) uint8_t pool[2 * STAGE_STRIDE];   // 49152

    const int tid = threadIdx.x;
    const int j0 = blockIdx.x * 32;
    const int b0 = blockIdx.y * 32;
    const int lane = tid & 31;
    const int warp = tid >> 5;
    const int mat = warp >> 3;            // 0: ih (x), 1: hh (h)
    const int mtile = (warp >> 2) & 1;    // 16-row half of the 32-row b tile
    const int npair = warp & 3;           // pair of 8-col n tiles

    const uint32_t smem_base = (uint32_t)__cvta_generic_to_shared(pool);

    // ---- copy mappings ----
    // W: 128 rows x 8 segs; each thread does segs wseg, wseg+4 of row tid>>2
    const int wrow = tid >> 2;
    const int wseg = tid & 3;
    const int wm = wrow >> 6;
    const int wg = ((wrow >> 5) & 1) * HID + j0 + (wrow & 31);
    const int8_t* wsrc = g_w8 + (((size_t)t * 2 + wm) * GCOLS + wg) * 1024;
    const uint32_t wdst0 = SW_OFF + swz(wrow, wseg * 16);
    const uint32_t wdst1 = SW_OFF + swz(wrow, (wseg + 4) * 16);

    // A: 64 rows x 8 segs; thread -> (x/h, row, seg)
    const int ahalf = tid >> 8;
    const int arow = (tid >> 3) & 31;
    const int aseg = tid & 7;
    const uint8_t* asrc = ahalf ? &g_h8[t & 1][b0 + arow][0] : &g_x8[t][b0 + arow][0];
    const uint32_t adst = (ahalf ? SH_OFF : SX_OFF) + swz(arow, aseg * 16);

    // ---- mma fragment addressing (swizzled) ----
    const int rowA = mtile * 16 + (lane >> 2);          // rows rowA, rowA+8 share (&7)
    const int xmA = (rowA & 7) << 4;
    const uint32_t aoff0 = (uint32_t)(rowA * 128) + (uint32_t)((lane & 3) * 4);
    const uint32_t aoff1 = aoff0 + 8 * 128;
    const int rowB = mat * 64 + npair * 16 + (lane >> 2);
    const int xmB = (rowB & 7) << 4;
    const uint32_t boff0 = (uint32_t)(rowB * 128) + (uint32_t)((lane & 3) * 4);
    const uint32_t boff1 = boff0 + 8 * 128;
    const uint32_t sAoff = mat ? SH_OFF : SX_OFF;

    int d[2][4] = {{0, 0, 0, 0}, {0, 0, 0, 0}};

    // ---- prologue: stages 0,1 ----
#pragma unroll
    for (int p = 0; p < 2; p++) {
        uint32_t sb = smem_base + p * STAGE_STRIDE;
        CP_ASYNC16(sb + wdst0, wsrc + p * 128 + wseg * 16);
        CP_ASYNC16(sb + wdst1, wsrc + p * 128 + (wseg + 4) * 16);
        CP_ASYNC16(sb + adst, asrc + p * 128 + aseg * 16);
        CP_COMMIT();
    }

    for (int kt = 0; kt < 8; kt++) {
        if (kt == 7) { CP_WAIT0(); } else { CP_WAIT1(); }
        __syncthreads();
        const uint8_t* stg = pool + (kt & 1) * STAGE_STRIDE;
        const uint8_t* sA = stg + sAoff;
        const uint8_t* sW = stg + SW_OFF;
#pragma unroll
        for (int ks = 0; ks < 4; ks++) {
            const int kb = ks * 32;
            uint32_t a[4];
            a[0] = *(const uint32_t*)(sA + aoff0 + (kb ^ xmA));
            a[1] = *(const uint32_t*)(sA + aoff1 + (kb ^ xmA));
            a[2] = *(const uint32_t*)(sA + aoff0 + ((kb + 16) ^ xmA));
            a[3] = *(const uint32_t*)(sA + aoff1 + ((kb + 16) ^ xmA));
            uint32_t br0[2], br1[2];
            br0[0] = *(const uint32_t*)(sW + boff0 + (kb ^ xmB));
            br0[1] = *(const uint32_t*)(sW + boff0 + ((kb + 16) ^ xmB));
            br1[0] = *(const uint32_t*)(sW + boff1 + (kb ^ xmB));
            br1[1] = *(const uint32_t*)(sW + boff1 + ((kb + 16) ^ xmB));
            mma_s8(d[0], a, br0);
            mma_s8(d[1], a, br1);
        }
        __syncthreads();
        if (kt + 2 < 8) {
            uint32_t sb = smem_base + (kt & 1) * STAGE_STRIDE;
            const int kk = (kt + 2) * 128;
            CP_ASYNC16(sb + wdst0, wsrc + kk + wseg * 16);
            CP_ASYNC16(sb + wdst1, wsrc + kk + (wseg + 4) * 16);
            CP_ASYNC16(sb + adst, asrc + kk + aseg * 16);
        }
        CP_COMMIT();
    }

    // ---- epilogue: fragments -> gsm (overlaid on dead stage-0 buffer) ----
    float* gsm = (float*)pool;   // [2][2][32][32]
#pragma unroll
    for (int tt = 0; tt < 2; tt++) {
        int ntile = 2 * npair + tt;
        int half = ntile >> 2;
        int cb = (ntile * 8 + (lane & 3) * 2) & 31;
        int rb = mtile * 16 + (lane >> 2);
        float* g = gsm + ((mat * 2 + half) * 32) * 32;
        g[rb * 32 + cb]           = (float)d[tt][0];
        g[rb * 32 + cb + 1]       = (float)d[tt][1];
        g[(rb + 8) * 32 + cb]     = (float)d[tt][2];
        g[(rb + 8) * 32 + cb + 1] = (float)d[tt][3];
    }
    __syncthreads();

    // ---- fused FSU elementwise (2 elements / thread) ----
#pragma unroll
    for (int i = 0; i < 2; i++) {
        int idx = tid + 512 * i;
        int bb = idx >> 5;
        int jl = idx & 31;
        int b = b0 + bb;
        int j = j0 + jl;
        int e = b * HID + j;

        float gi_f = gsm[(0 * 32 + bb) * 32 + jl] + g_C[0][t * GCOLS + j];
        float gi_n = gsm[(1 * 32 + bb) * 32 + jl] + g_C[0][t * GCOLS + HID + j];
        float gh_f = gsm[(2 * 32 + bb) * 32 + jl] + g_C[1][t * GCOLS + j];
        float gh_n = gsm[(3 * 32 + bb) * 32 + jl] + g_C[1][t * GCOLS + HID + j];

        float h  = (float)g_h8[t & 1][b][j];
        float a1 = g_acc[0][e], a2 = g_acc[1][e], a3 = g_acc[2][e];
        float a4 = g_acc[3][e], a5 = g_acc[4][e], a6 = g_acc[5][e];
        uint32_t m1 = g_mul[0][e], m2 = g_mul[1][e], m3 = g_mul[2][e];

        a1 = clampA(a1 + (gi_f + gh_f) - 1024.5f);
        float fg_in = (a1 >= 1.0f) ? 1.0f : 0.0f;  a1 -= fg_in;

        a2 = clampA(a2 + fg_in + 1.0f);
        float fg = (a2 >= 2.0f) ? 1.0f : 0.0f;     a2 -= 2.0f * fg;

        a3 = clampA(a3 + gh_n - 512.0f);
        float hnb = (a3 >= 1.0f) ? 1.0f : 0.0f;    a3 -= hnb;

        float ng_prod = fsu_mul_upd(m1, fg, hnb);

        a4 = clampA(a4 + gi_n - 512.0f);
        float inb = (a4 >= 1.0f) ? 1.0f : 0.0f;    a4 -= inb;

        a5 = clampA(a5 + (inb + ng_prod) - 0.5f);
        float ng = (a5 >= 1.0f) ? 1.0f : 0.0f;     a5 -= ng;

        float fgi_prod = fsu_mul_upd(m2, 1.0f - fg, ng);
        float fg_prod  = fsu_mul_upd(m3, fg, h);

        a6 = clampA(a6 + (ng + fgi_prod + fg_prod) - 1.0f);
        float hy = (a6 >= 1.0f) ? 1.0f : 0.0f;     a6 -= hy;

        g_acc[0][e] = a1; g_acc[1][e] = a2; g_acc[2][e] = a3;
        g_acc[3][e] = a4; g_acc[4][e] = a5; g_acc[5][e] = a6;
        g_mul[0][e] = m1; g_mul[1][e] = m2; g_mul[2][e] = m3;

        g_h8[(t + 1) & 1][b][j] = (uint8_t)(int)hy;
        out[((size_t)t * BATCH + b) * HID + j] = hy;
    }
}

extern "C" void kernel_launch(void* const* d_in, const int* in_sizes, int n_in,
                              void* d_out, int out_size) {
    const float* x_bits = (const float*)d_in[0];
    const float* hx0    = (const float*)d_in[1];
    const float* wih    = (const float*)d_in[2];
    const float* bih    = (const float*)d_in[3];
    const float* whh    = (const float*)d_in[4];
    const float* bhh    = (const float*)d_in[5];
    float* out = (float*)d_out;

    rng_init_kernel<<<1, 32>>>();

    const long long qtotal = 2LL * GCOLS * KTOT;
    quant_kernel<<<(int)((qtotal + 255) / 256), 256>>>(wih, bih, whh, bhh);

    swi_kernel<<<2 * GCOLS, 128>>>();

    expand_kernel<<<65536, 256>>>();

    const long long xtotal = (long long)T_STEPS * BATCH * INP;
    xpack_kernel<<<(int)((xtotal / 4 + 255) / 256), 256>>>(x_bits);

    state_init_kernel<<<(BATCH * HID + 255) / 256, 256>>>(hx0);

    dim3 grid(HID / 32, BATCH / 32);
    for (int t = 0; t < T_STEPS; t++) {
        step_kernel<<<grid, 512>>>(t, out);
    }
}

// round 8
// speedup vs baseline: 3.0222x; 1.1091x over previous
#include <cuda_runtime.h>
#include <cstdint>

#define T_STEPS 64
#define BATCH   128
#define HID     1024
#define INP     1024
#define KTOT    1025
#define GCOLS   2048
#define SRC_PITCH 1032          // u16 pitch
#define ACC_LIM 256.0f

// smem layout (dynamic, 64KB): two 24KB stages + 16KB gsm exchange
//   stage: sX 32*128=4096 | sH 4096 | sW 128*128=16384
#define STAGE_STRIDE 24576
#define SX_OFF 0
#define SH_OFF 4096
#define SW_OFF 8192
#define GSM_OFF 49152
#define SMEM_TOTAL 65536

// ---- static device state (no dynamic allocation) ----
__device__ __align__(16) uint16_t g_src[2][GCOLS * SRC_PITCH];   // quantized weights (u16)
__device__ float    g_C[2][T_STEPS * GCOLS];                     // per-(t,col) gate constant
__device__ int      g_rngW[256];
__device__ int      g_rngWI[256];
__device__ int      g_rngM[16];
__device__ __align__(16) int8_t   g_w8[(size_t)T_STEPS * 2 * GCOLS * 1024]; // expanded W' in {-1,0,1}
__device__ __align__(16) uint8_t  g_x8[T_STEPS][BATCH][INP];     // x as s8 {0,1}
__device__ __align__(16) uint8_t  g_h8[2][BATCH][HID];           // h double buffer, s8 {0,1}
__device__ int      g_bar;                                       // persistent-kernel step barrier

// ---- numpy RandomState(seed).permutation(n), bit-exact ----
__device__ void mt_fill_perm(uint32_t seed, int n, int* out) {
    uint32_t mt[624];
    uint32_t s = seed;
    for (int i = 0; i < 624; i++) { mt[i] = s; s = 1812433253u * (s ^ (s >> 30)) + (uint32_t)i + 1u; }
    int pos = 624;
    int arr[256];
    for (int i = 0; i < n; i++) arr[i] = i;
    for (int i = n - 1; i > 0; i--) {
        uint32_t mask = (uint32_t)i;
        mask |= mask >> 1; mask |= mask >> 2; mask |= mask >> 4; mask |= mask >> 8; mask |= mask >> 16;
        uint32_t j;
        do {
            if (pos >= 624) {
                for (int k = 0; k < 624; k++) {
                    uint32_t y = (mt[k] & 0x80000000u) | (mt[(k + 1) % 624] & 0x7fffffffu);
                    uint32_t v = mt[(k + 397) % 624] ^ (y >> 1);
                    if (y & 1u) v ^= 0x9908b0dfu;
                    mt[k] = v;
                }
                pos = 0;
            }
            uint32_t y = mt[pos++];
            y ^= y >> 11; y ^= (y << 7) & 0x9d2c5680u; y ^= (y << 15) & 0xefc60000u; y ^= y >> 18;
            j = y & mask;
        } while (j > (uint32_t)i);
        int tmp = arr[i]; arr[i] = arr[j]; arr[j] = tmp;
    }
    for (int i = 0; i < n; i++) out[i] = arr[i];
}

__global__ void rng_init_kernel() {
    int t = threadIdx.x;
    if (t == 0) mt_fill_perm(0u, 256, g_rngW);
    else if (t == 1) mt_fill_perm(1u, 256, g_rngWI);
    else if (t == 2) mt_fill_perm(2u, 16, g_rngM);
}

// src = round_half_even((clip(w,-1,1)+1)*0.5*256)
__global__ void quant_kernel(const float* __restrict__ wih, const float* __restrict__ bih,
                             const float* __restrict__ whh, const float* __restrict__ bhh) {
    long long idx = (long long)blockIdx.x * blockDim.x + threadIdx.x;
    const long long total = 2LL * GCOLS * KTOT;
    if (idx >= total) return;
    int m = (int)(idx / (GCOLS * KTOT));
    int r = (int)(idx % (GCOLS * KTOT));
    int j = r / KTOT, k = r % KTOT;
    const float* w = m ? whh : wih;
    const float* b = m ? bhh : bih;
    float v = (k < INP) ? w[(size_t)j * INP + k] : b[j];
    v = fminf(fmaxf(v, -1.0f), 1.0f);
    v = (v + 1.0f) * 0.5f * 256.0f;
    g_src[m][(size_t)j * SRC_PITCH + k] = (uint16_t)__float2int_rn(v);
}

__device__ __forceinline__ int wval(int s, int rp, int ri) {
    return (s > rp) + (s > ri) - 1;
}

// per (m,row): histogram over src values, suffix counts, fold bias-column W'
__global__ void swi_kernel() {
    int m = blockIdx.x >> 11;
    int j = blockIdx.x & 2047;
    __shared__ int hist[257];
    __shared__ int sfx[258];
    for (int i = threadIdx.x; i < 257; i += blockDim.x) hist[i] = 0;
    __syncthreads();
    const uint16_t* row = &g_src[m][(size_t)j * SRC_PITCH];
    for (int k = threadIdx.x; k < KTOT; k += blockDim.x) atomicAdd(&hist[row[k]], 1);
    __syncthreads();
    if (threadIdx.x == 0) {
        int s = 0; sfx[257] = 0;
        for (int v = 256; v >= 0; v--) { s += hist[v]; sfx[v] = s; }
    }
    __syncthreads();
    int sb = (int)row[INP];
    for (int t = threadIdx.x; t < T_STEPS; t += blockDim.x) {
        int ri = g_rngWI[t], rp = g_rngW[t];
        g_C[m][t * GCOLS + j] = (float)(1025 - sfx[ri + 1] + wval(sb, rp, ri));
    }
}

// SIMD-halfword expansion: 4 u16 -> 4 s8 in {-1,0,1}
__device__ __forceinline__ uint32_t exp4(uint32_t lo, uint32_t hi, uint32_t rp2, uint32_t ri2) {
    uint32_t t0 = __vsetgtu2(lo, rp2) + __vsetgtu2(lo, ri2);   // per-half {0,1,2}
    uint32_t t1 = __vsetgtu2(hi, rp2) + __vsetgtu2(hi, ri2);
    t0 = (t0 + 0x7FFF7FFFu) ^ 0x80008000u;                     // per-half -1 -> s16 {-1,0,1}
    t1 = (t1 + 0x7FFF7FFFu) ^ 0x80008000u;
    return __byte_perm(t0, t1, 0x6420);                        // low bytes of 4 halfwords
}

__global__ __launch_bounds__(256) void expand_kernel() {
    int idx = blockIdx.x * 256 + threadIdx.x;   // 16,777,216 threads
    int k16  = idx & 63;
    int gcol = (idx >> 6) & 2047;
    int m    = (idx >> 17) & 1;
    int t    = idx >> 18;
    uint32_t rp2 = (uint32_t)g_rngW[t] * 0x10001u;
    uint32_t ri2 = (uint32_t)g_rngWI[t] * 0x10001u;
    const uint16_t* src = &g_src[m][(size_t)gcol * SRC_PITCH + k16 * 16];
    uint4 q0 = *(const uint4*)src;
    uint4 q1 = *(const uint4*)(src + 8);
    uint4 o;
    o.x = exp4(q0.x, q0.y, rp2, ri2);
    o.y = exp4(q0.z, q0.w, rp2, ri2);
    o.z = exp4(q1.x, q1.y, rp2, ri2);
    o.w = exp4(q1.z, q1.w, rp2, ri2);
    *(uint4*)(g_w8 + (size_t)idx * 16) = o;
}

// x float {0,1} -> s8 bytes, 4 per thread
__global__ void xpack_kernel(const float* __restrict__ x) {
    long long i = (long long)blockIdx.x * blockDim.x + threadIdx.x;
    long long base = i * 4;
    const long long total = (long long)T_STEPS * BATCH * INP;
    if (base >= total) return;
    float4 v = *(const float4*)(x + base);
    uchar4 o;
    o.x = (uint8_t)(int)v.x; o.y = (uint8_t)(int)v.y;
    o.z = (uint8_t)(int)v.z; o.w = (uint8_t)(int)v.w;
    *(uchar4*)(&g_x8[0][0][0] + base) = o;
}

__global__ void state_init_kernel(const float* __restrict__ hx0) {
    int e = blockIdx.x * blockDim.x + threadIdx.x;
    if (e == 0) g_bar = 0;                         // reset persistent barrier each call
    if (e >= BATCH * HID) return;
    (&g_h8[0][0][0])[e] = (uint8_t)(int)hx0[e];
}

__device__ __forceinline__ float clampA(float v) { return fminf(fmaxf(v, -ACC_LIM), ACC_LIM); }

__device__ __forceinline__ float fsu_mul_upd(uint32_t& m, float in0, float in1) {
    uint32_t sr = m & 0xFu;
    sr = (sr >> 1) | (((uint32_t)in1) << 3);
    int cnt = __popc(sr) * 4;
    uint32_t ip = (m >> 8) & 0xFFu;
    uint32_t ii = (m >> 16) & 0xFFu;
    float bp = (cnt > g_rngM[ip & 15u]) ? 1.0f : 0.0f;
    float bi = (cnt > g_rngM[ii & 15u]) ? 1.0f : 0.0f;
    float outv = in0 * bp + (1.0f - in0) * (1.0f - bi);
    uint32_t i0 = (uint32_t)in0;
    ip += i0; ii += 1u - i0;
    m = sr | ((ip & 0xFFu) << 8) | ((ii & 0xFFu) << 16);
    return outv;
}

__device__ __forceinline__ void mma_s8(int* d, const uint32_t* a, const uint32_t* b) {
    asm volatile(
        "mma.sync.aligned.m16n8k32.row.col.s32.s8.s8.s32 "
        "{%0,%1,%2,%3}, {%4,%5,%6,%7}, {%8,%9}, {%0,%1,%2,%3};"
        : "+r"(d[0]), "+r"(d[1]), "+r"(d[2]), "+r"(d[3])
        : "r"(a[0]), "r"(a[1]), "r"(a[2]), "r"(a[3]), "r"(b[0]), "r"(b[1]));
}

#define CP_ASYNC16(dst_u32, src_ptr) \
    asm volatile("cp.async.cg.shared.global [%0], [%1], 16;" :: "r"(dst_u32), "l"(src_ptr))
#define CP_COMMIT() asm volatile("cp.async.commit_group;" ::)
#define CP_WAIT1()  asm volatile("cp.async.wait_group 1;" ::)
#define CP_WAIT0()  asm volatile("cp.async.wait_group 0;" ::)

// swizzle: within a 128B row, 16B chunk index ^= (row & 7)
__device__ __forceinline__ uint32_t swz(int row, int colbyte) {
    return (uint32_t)(row * 128 + (colbyte ^ ((row & 7) << 4)));
}

// ---- persistent fused kernel: all 64 steps, grid barrier between steps ----
// grid (32 j-blocks, 4 b-blocks) = 128 CTAs (all co-resident), 512 threads
__global__ __launch_bounds__(512, 1) void step_all_kernel(float* __restrict__ out) {
    extern __shared__ __align__(16) uint8_t pool[];

    const int tid = threadIdx.x;
    const int j0 = blockIdx.x * 32;
    const int b0 = blockIdx.y * 32;
    const int lane = tid & 31;
    const int warp = tid >> 5;
    const int mat = warp >> 3;            // 0: ih (x), 1: hh (h)
    const int mtile = (warp >> 2) & 1;
    const int npair = warp & 3;
    const int nCTA = gridDim.x * gridDim.y;   // 128

    const uint32_t smem_base = (uint32_t)__cvta_generic_to_shared(pool);
    float* gsm = (float*)(pool + GSM_OFF);    // [4][32][32]

    // ---- copy mappings ----
    const int wrow = tid >> 2;
    const int wseg = tid & 3;
    const int wm = wrow >> 6;
    const int wg = ((wrow >> 5) & 1) * HID + j0 + (wrow & 31);
    const int8_t* wbase = g_w8 + ((size_t)wm * GCOLS + wg) * 1024;
    const size_t wtstride = (size_t)2 * GCOLS * 1024;
    const uint32_t wdst0 = SW_OFF + swz(wrow, wseg * 16);
    const uint32_t wdst1 = SW_OFF + swz(wrow, (wseg + 4) * 16);

    const int ahalf = tid >> 8;
    const int arow = (tid >> 3) & 31;
    const int aseg = tid & 7;
    const uint32_t adst = (ahalf ? SH_OFF : SX_OFF) + swz(arow, aseg * 16);

    // ---- mma fragment addressing (swizzled) ----
    const int rowA = mtile * 16 + (lane >> 2);
    const int xmA = (rowA & 7) << 4;
    const uint32_t aoff0 = (uint32_t)(rowA * 128) + (uint32_t)((lane & 3) * 4);
    const uint32_t aoff1 = aoff0 + 8 * 128;
    const int rowB = mat * 64 + npair * 16 + (lane >> 2);
    const int xmB = (rowB & 7) << 4;
    const uint32_t boff0 = (uint32_t)(rowB * 128) + (uint32_t)((lane & 3) * 4);
    const uint32_t boff1 = boff0 + 8 * 128;
    const uint32_t sAoff = mat ? SH_OFF : SX_OFF;

    // ---- per-element constants (2 elems/thread, fixed across t) ----
    int EB[2], EJ[2], EBB[2], EJL[2];
#pragma unroll
    for (int i = 0; i < 2; i++) {
        int idx = tid + 512 * i;
        EBB[i] = idx >> 5; EJL[i] = idx & 31;
        EB[i] = b0 + EBB[i]; EJ[i] = j0 + EJL[i];
    }

    // ---- register-resident FSU state ----
    float A1[2] = {0, 0}, A2[2] = {0, 0}, A3[2] = {0, 0};
    float A4[2] = {0, 0}, A5[2] = {0, 0}, A6[2] = {0, 0};
    uint32_t M1[2] = {10u, 10u}, M2[2] = {10u, 10u}, M3[2] = {10u, 10u};

    // ---- prologue: stage 0,1 of t=0 (W + x + h) ----
    {
        const int8_t* w0 = wbase;
        const uint8_t* xs = &g_x8[0][b0 + arow][0];
        const uint8_t* hs = &g_h8[0][b0 + arow][0];
#pragma unroll
        for (int p = 0; p < 2; p++) {
            uint32_t sb = smem_base + p * STAGE_STRIDE;
            CP_ASYNC16(sb + wdst0, w0 + p * 128 + wseg * 16);
            CP_ASYNC16(sb + wdst1, w0 + p * 128 + (wseg + 4) * 16);
            CP_ASYNC16(sb + adst, (ahalf ? hs : xs) + p * 128 + aseg * 16);
            CP_COMMIT();
        }
    }

    for (int t = 0; t < T_STEPS; t++) {
        const int8_t* wsrc_t1 = wbase + (size_t)(t + 1) * wtstride;
        const uint8_t* xsrc_t = &g_x8[t][b0 + arow][0];
        const uint8_t* hsrc_t = &g_h8[t & 1][b0 + arow][0];
        const uint8_t* xsrc_t1 = &g_x8[(t + 1) & 63][b0 + arow][0];

        int d[2][4] = {{0, 0, 0, 0}, {0, 0, 0, 0}};

        for (int kt = 0; kt < 8; kt++) {
            if (kt == 0) { CP_WAIT0(); } else { CP_WAIT1(); }
            __syncthreads();
            const uint8_t* stg = pool + (kt & 1) * STAGE_STRIDE;
            const uint8_t* sA = stg + sAoff;
            const uint8_t* sW = stg + SW_OFF;
#pragma unroll
            for (int ks = 0; ks < 4; ks++) {
                const int kb = ks * 32;
                uint32_t a[4];
                a[0] = *(const uint32_t*)(sA + aoff0 + (kb ^ xmA));
                a[1] = *(const uint32_t*)(sA + aoff1 + (kb ^ xmA));
                a[2] = *(const uint32_t*)(sA + aoff0 + ((kb + 16) ^ xmA));
                a[3] = *(const uint32_t*)(sA + aoff1 + ((kb + 16) ^ xmA));
                uint32_t br0[2], br1[2];
                br0[0] = *(const uint32_t*)(sW + boff0 + (kb ^ xmB));
                br0[1] = *(const uint32_t*)(sW + boff0 + ((kb + 16) ^ xmB));
                br1[0] = *(const uint32_t*)(sW + boff1 + (kb ^ xmB));
                br1[1] = *(const uint32_t*)(sW + boff1 + ((kb + 16) ^ xmB));
                mma_s8(d[0], a, br0);
                mma_s8(d[1], a, br1);
            }
            __syncthreads();
            if (kt < 6) {
                uint32_t sb = smem_base + (kt & 1) * STAGE_STRIDE;
                const int kk = (kt + 2) * 128;
                CP_ASYNC16(sb + wdst0, wbase + (size_t)t * wtstride + kk + wseg * 16);
                CP_ASYNC16(sb + wdst1, wbase + (size_t)t * wtstride + kk + (wseg + 4) * 16);
                CP_ASYNC16(sb + adst, (ahalf ? hsrc_t : xsrc_t) + kk + aseg * 16);
            } else if (t + 1 < T_STEPS) {
                // prefetch W + x of (t+1, chunk kt-6) — overlaps epilogue/barrier
                const int cc = kt - 6;
                uint32_t sb = smem_base + cc * STAGE_STRIDE;
                CP_ASYNC16(sb + wdst0, wsrc_t1 + cc * 128 + wseg * 16);
                CP_ASYNC16(sb + wdst1, wsrc_t1 + cc * 128 + (wseg + 4) * 16);
                if (!ahalf) CP_ASYNC16(sb + adst, xsrc_t1 + cc * 128 + aseg * 16);
            }
            CP_COMMIT();
        }

        // ---- epilogue: fragments -> gsm ----
#pragma unroll
        for (int tt = 0; tt < 2; tt++) {
            int ntile = 2 * npair + tt;
            int half = ntile >> 2;
            int cb = (ntile * 8 + (lane & 3) * 2) & 31;
            int rb = mtile * 16 + (lane >> 2);
            float* g = gsm + ((mat * 2 + half) * 32) * 32;
            g[rb * 32 + cb]           = (float)d[tt][0];
            g[rb * 32 + cb + 1]       = (float)d[tt][1];
            g[(rb + 8) * 32 + cb]     = (float)d[tt][2];
            g[(rb + 8) * 32 + cb + 1] = (float)d[tt][3];
        }
        __syncthreads();

        // ---- fused FSU elementwise (register state) ----
#pragma unroll
        for (int i = 0; i < 2; i++) {
            int b = EB[i], j = EJ[i], bb = EBB[i], jl = EJL[i];

            float gi_f = gsm[(0 * 32 + bb) * 32 + jl] + g_C[0][t * GCOLS + j];
            float gi_n = gsm[(1 * 32 + bb) * 32 + jl] + g_C[0][t * GCOLS + HID + j];
            float gh_f = gsm[(2 * 32 + bb) * 32 + jl] + g_C[1][t * GCOLS + j];
            float gh_n = gsm[(3 * 32 + bb) * 32 + jl] + g_C[1][t * GCOLS + HID + j];

            float h = (float)__ldcg(&g_h8[t & 1][b][j]);   // L2 (cross-CTA coherent)

            A1[i] = clampA(A1[i] + (gi_f + gh_f) - 1024.5f);
            float fg_in = (A1[i] >= 1.0f) ? 1.0f : 0.0f;  A1[i] -= fg_in;

            A2[i] = clampA(A2[i] + fg_in + 1.0f);
            float fg = (A2[i] >= 2.0f) ? 1.0f : 0.0f;     A2[i] -= 2.0f * fg;

            A3[i] = clampA(A3[i] + gh_n - 512.0f);
            float hnb = (A3[i] >= 1.0f) ? 1.0f : 0.0f;    A3[i] -= hnb;

            float ng_prod = fsu_mul_upd(M1[i], fg, hnb);

            A4[i] = clampA(A4[i] + gi_n - 512.0f);
            float inb = (A4[i] >= 1.0f) ? 1.0f : 0.0f;    A4[i] -= inb;

            A5[i] = clampA(A5[i] + (inb + ng_prod) - 0.5f);
            float ng = (A5[i] >= 1.0f) ? 1.0f : 0.0f;     A5[i] -= ng;

            float fgi_prod = fsu_mul_upd(M2[i], 1.0f - fg, ng);
            float fg_prod  = fsu_mul_upd(M3[i], fg, h);

            A6[i] = clampA(A6[i] + (ng + fgi_prod + fg_prod) - 1.0f);
            float hy = (A6[i] >= 1.0f) ? 1.0f : 0.0f;     A6[i] -= hy;

            g_h8[(t + 1) & 1][b][j] = (uint8_t)(int)hy;
            out[((size_t)t * BATCH + b) * HID + j] = hy;
        }

        // ---- grid barrier + post-barrier h prefetch for t+1 ----
        if (t + 1 < T_STEPS) {
            __threadfence();
            __syncthreads();
            if (tid == 0) {
                atomicAdd(&g_bar, 1);
                const int tgt = nCTA * (t + 1);
                while (*(volatile int*)&g_bar < tgt) { }
                __threadfence();
            }
            __syncthreads();
            if (ahalf) {
                const uint8_t* hs1 = &g_h8[(t + 1) & 1][b0 + arow][0];
                CP_ASYNC16(smem_base + 0 * STAGE_STRIDE + adst, hs1 + aseg * 16);
                CP_ASYNC16(smem_base + 1 * STAGE_STRIDE + adst, hs1 + 128 + aseg * 16);
            }
            CP_COMMIT();
        }
    }
}

extern "C" void kernel_launch(void* const* d_in, const int* in_sizes, int n_in,
                              void* d_out, int out_size) {
    const float* x_bits = (const float*)d_in[0];
    const float* hx0    = (const float*)d_in[1];
    const float* wih    = (const float*)d_in[2];
    const float* bih    = (const float*)d_in[3];
    const float* whh    = (const float*)d_in[4];
    const float* bhh    = (const float*)d_in[5];
    float* out = (float*)d_out;

    cudaFuncSetAttribute(step_all_kernel, cudaFuncAttributeMaxDynamicSharedMemorySize, SMEM_TOTAL);

    rng_init_kernel<<<1, 32>>>();

    const long long qtotal = 2LL * GCOLS * KTOT;
    quant_kernel<<<(int)((qtotal + 255) / 256), 256>>>(wih, bih, whh, bhh);

    swi_kernel<<<2 * GCOLS, 128>>>();

    expand_kernel<<<65536, 256>>>();

    const long long xtotal = (long long)T_STEPS * BATCH * INP;
    xpack_kernel<<<(int)((xtotal / 4 + 255) / 256), 256>>>(x_bits);

    state_init_kernel<<<(BATCH * HID + 255) / 256, 256>>>(hx0);

    dim3 grid(HID / 32, BATCH / 32);
    step_all_kernel<<<grid, 512, SMEM_TOTAL>>>(out);
}